// round 15
// baseline (speedup 1.0000x reference)
#include <cuda_runtime.h>
#include <math.h>
#include <stdint.h>

#define B_  8
#define S_  2048
#define D_  64
#define BM  64
#define BN  64
#define NT  256
#define CW  8           // kv tiles per chunk
#define NCHUNK 80       // chunks per batch
#define TILES 32        // 64-row tiles per batch

typedef uint32_t u32;

// smem word offsets
#define QP_O 0                    // [8kc][64r][4tig] uint4 (hi,hi+4,lo,lo+4)
#define KP_O (QP_O + 8192)
#define VP_O (KP_O + 8192)        // [8kcv][64d][8] packed uint2 (V[k],V[k+4])
#define SM_WORDS (VP_O + 4096)
#define SM_BYTES (SM_WORDS * 4)   // 81920 B -> 2 CTAs/SM

__device__ float g_Lsum[B_ * S_];
__device__ u32 g_QP[B_ * TILES * 8192];   // pre-packed Q tiles (8 MB)
__device__ u32 g_KP[B_ * TILES * 8192];   // pre-packed K tiles (8 MB)
__device__ u32 g_VP[B_ * TILES * 4096];   // pre-packed V tiles (4 MB)

__device__ __forceinline__ u32 f2tf(float x) {
    u32 r; asm("cvt.rna.tf32.f32 %0, %1;" : "=r"(r) : "f"(x)); return r;
}
__device__ __forceinline__ u32 smem_u32(const void* p) {
    u32 a; asm("{ .reg .u64 t; cvta.to.shared.u64 t, %1; cvt.u32.u64 %0, t; }" : "=r"(a) : "l"(p));
    return a;
}
__device__ __forceinline__ void cpa16(u32 dst, const void* src) {
    asm volatile("cp.async.cg.shared.global [%0], [%1], 16;" :: "r"(dst), "l"(src) : "memory");
}
#define CPA_COMMIT() asm volatile("cp.async.commit_group;" ::: "memory")
#define CPA_WAIT1()  asm volatile("cp.async.wait_group 1;" ::: "memory")
#define CPA_WAIT0()  asm volatile("cp.async.wait_group 0;" ::: "memory")

__device__ __forceinline__ void mma8(float* d, const u32* a, u32 b0, u32 b1) {
    asm volatile("mma.sync.aligned.m16n8k8.row.col.f32.tf32.tf32.f32 "
        "{%0,%1,%2,%3}, {%4,%5,%6,%7}, {%8,%9}, {%0,%1,%2,%3};"
        : "+f"(d[0]), "+f"(d[1]), "+f"(d[2]), "+f"(d[3])
        : "r"(a[0]), "r"(a[1]), "r"(a[2]), "r"(a[3]), "r"(b0), "r"(b1));
}

// Prep: pack Q/K (hi/lo tf32) and V (tf32) into MMA smem-image layouts in
// global scratch; zero O and Lsum. Grid (TILES, B_), 256 threads.
__global__ void prep_k(const float* __restrict__ Q, const float* __restrict__ K,
                       const float* __restrict__ V, float* __restrict__ O)
{
    const int blk = blockIdx.x, b = blockIdx.y;
    const int tid = threadIdx.x;
    const int row = tid & 63, db = (tid >> 6) * 16;
    const int rot = (row >> 1) & 3;

    // Q and K: identical hi/lo pack
    const float* srcs[2] = { Q + ((size_t)(b * S_ + blk * 64 + row)) * D_ + db,
                             K + ((size_t)(b * S_ + blk * 64 + row)) * D_ + db };
    u32* dsts[2] = { g_QP + (b * TILES + blk) * 8192,
                     g_KP + (b * TILES + blk) * 8192 };
#pragma unroll
    for (int m = 0; m < 2; m++) {
        const float4* src = (const float4*)srcs[m];
        float e[16];
#pragma unroll
        for (int j = 0; j < 4; j++) { float4 x = src[j]; e[4*j]=x.x; e[4*j+1]=x.y; e[4*j+2]=x.z; e[4*j+3]=x.w; }
#pragma unroll
        for (int cc = 0; cc < 2; cc++) {
            const int kc = (db >> 3) + cc;
#pragma unroll
            for (int j = 0; j < 4; j++) {
                float h0f = e[cc*8 + j], h1f = e[cc*8 + j + 4];
                u32 h0 = f2tf(h0f), h1 = f2tf(h1f);
                u32 l0w = f2tf(h0f - __uint_as_float(h0));
                u32 l1w = f2tf(h1f - __uint_as_float(h1));
                *(uint4*)&dsts[m][kc*1024 + row*16 + (((j + rot) & 3) << 2)] =
                    make_uint4(h0, h1, l0w, l1w);
            }
        }
    }

    // V pack
    {
        const float4* src = (const float4*)(V + ((size_t)(b * S_ + blk * 64 + row)) * D_ + db);
        float e[16];
#pragma unroll
        for (int j = 0; j < 4; j++) { float4 x = src[j]; e[4*j]=x.x; e[4*j+1]=x.y; e[4*j+2]=x.z; e[4*j+3]=x.w; }
        u32* vdst = g_VP + (b * TILES + blk) * 4096;
        const int kcv = row >> 3, tv = row & 3, sl = (row >> 2) & 1;
#pragma unroll
        for (int i = 0; i < 16; i++) {
            const int d = db + i;
            vdst[kcv*512 + d*8 + (((tv + (d >> 1)) & 3) << 1) + sl] = f2tf(e[i]);
        }
    }

    // zero O (coalesced) + Lsum
    const int gidx = (b * TILES + blk) * NT + tid;   // 0..65535
    float4* O4 = (float4*)O;
#pragma unroll
    for (int j = 0; j < 4; j++)
        O4[j * 65536 + gidx] = make_float4(0.f, 0.f, 0.f, 0.f);
    if (gidx < (B_ * S_) / 4)
        ((float4*)g_Lsum)[gidx] = make_float4(0.f, 0.f, 0.f, 0.f);
}

__global__ void norm_k(float* __restrict__ out, int n4) {
    int i = blockIdx.x * blockDim.x + threadIdx.x;
    if (i >= n4) return;
    float inv = 1.f / g_Lsum[i >> 4];
    float4 v = ((float4*)out)[i];
    v.x *= inv; v.y *= inv; v.z *= inv; v.w *= inv;
    ((float4*)out)[i] = v;
}

// Causal flash attention, mma.sync tf32 (3xtf32 QK^T, 1xtf32 PV), split-K chunks.
// All operands pre-packed by prep_k; tiles stream in via cp.async groups with
// KP hidden under exp+MMA2 and VP hidden under MMA1.
__global__ __launch_bounds__(NT, 2) void fa_chunk(float* __restrict__ O)
{
    extern __shared__ u32 sm[];
    const u32 sb = smem_u32(sm);
    const int tid  = threadIdx.x;
    const int lane = tid & 31;
    const int gid  = lane >> 2;
    const int tig  = lane & 3;
    const int rw   = (tid >> 5) >> 1;
    const int cw   = (tid >> 5) & 1;
    const int b    = blockIdx.y;

    // ---- decode (qb, chunk) ----
    int qb, c;
    {
        const int i = blockIdx.x;
        if (i < 8)       { qb = i; c = 0; }
        else if (i < 24) { int j = i - 8;  qb = 8  + (j >> 1); c = j & 1; }
        else if (i < 48) { int j = i - 24; qb = 16 + j / 3;    c = j - 3 * (j / 3); }
        else             { int j = i - 48; qb = 24 + (j >> 2); c = j & 3; }
    }
    const int t0 = c * CW;
    const int t1 = min(t0 + CW, qb + 1);
    const int qbase = qb * BM;
    const int rq   = rw * 16 + gid;
    const int sw   = (tig + (gid >> 1)) & 3;
    const int srcA = (lane & ~3) | (tig >> 1);
    const int srcB = srcA + 2;
    const u32 comp = tig & 1;

    // ---- prologue: cp.async QP + KP(t0) as one group, VP(t0) as another ----
    {
        const u32* qsrc = g_QP + (b * TILES + qb) * 8192;
        const u32* ksrc = g_KP + (b * TILES + t0) * 8192;
#pragma unroll
        for (int j = 0; j < 8; j++) {
            const int g = tid * 8 + j;
            cpa16(sb + (QP_O + g * 4) * 4, qsrc + g * 4);
        }
#pragma unroll
        for (int j = 0; j < 8; j++) {
            const int g = tid * 8 + j;
            cpa16(sb + (KP_O + g * 4) * 4, ksrc + g * 4);
        }
        CPA_COMMIT();
        const u32* vsrc = g_VP + (b * TILES + t0) * 4096;
#pragma unroll
        for (int j = 0; j < 4; j++) {
            const int g = tid * 4 + j;
            cpa16(sb + (VP_O + g * 4) * 4, vsrc + g * 4);
        }
        CPA_COMMIT();
    }

    float o[8][4];
#pragma unroll
    for (int nb = 0; nb < 8; nb++)
#pragma unroll
        for (int cc = 0; cc < 4; cc++) o[nb][cc] = 0.f;
    float l0 = 0.f, l1 = 0.f;
    const int gr0 = qbase + rq, gr1 = gr0 + 8;

    for (int t = t0; t < t1; t++) {
        const bool more = (t + 1 < t1);
        // invariant entering: outstanding groups = [gk(t), gv(t)]
        CPA_WAIT1();       // gk(t) done: QP (t0) + KP(t) landed
        __syncthreads();   // visible to all

        // ---- MMA1: S = Q @ K^T (3xtf32), this warp's 32-key half ----
        float s[4][4];
#pragma unroll
        for (int nb = 0; nb < 4; nb++)
#pragma unroll
            for (int cc = 0; cc < 4; cc++) s[nb][cc] = 0.f;
#pragma unroll
        for (int kc = 0; kc < 8; kc++) {
            uint4 qa = *(const uint4*)&sm[QP_O + kc*1024 + rq*16 + (sw << 2)];
            uint4 qc = *(const uint4*)&sm[QP_O + kc*1024 + (rq+8)*16 + (sw << 2)];
            u32 ah[4] = { qa.x, qc.x, qa.y, qc.y };
            u32 al[4] = { qa.z, qc.z, qa.w, qc.w };
#pragma unroll
            for (int nb = 0; nb < 4; nb++) {
                const int key = cw * 32 + nb * 8 + gid;
                uint4 kb = *(const uint4*)&sm[KP_O + kc*1024 + key*16 + (sw << 2)];
                mma8(s[nb], ah, kb.x, kb.y);
                mma8(s[nb], al, kb.x, kb.y);
                mma8(s[nb], ah, kb.z, kb.w);
            }
        }
        __syncthreads();   // all MMA1 done: KP(t) free

        // ---- refill KP with t+1 (hidden under exp + MMA2) ----
        if (more) {
            const u32* ksrc = g_KP + (b * TILES + t + 1) * 8192;
#pragma unroll
            for (int j = 0; j < 8; j++) {
                const int g = tid * 8 + j;
                cpa16(sb + (KP_O + g * 4) * 4, ksrc + g * 4);
            }
            CPA_COMMIT();
        }

        // ---- exp (+ causal mask on diagonal tile), l accumulation ----
        const bool diag = (t == qb);
#pragma unroll
        for (int nb = 0; nb < 4; nb++) {
            const int cg = t * BN + cw * 32 + nb * 8 + 2 * tig;
            float p0, p1, p2, p3;
            if (diag) {
                p0 = (cg     <= gr0) ? __expf(s[nb][0]) : 0.f;
                p1 = (cg + 1 <= gr0) ? __expf(s[nb][1]) : 0.f;
                p2 = (cg     <= gr1) ? __expf(s[nb][2]) : 0.f;
                p3 = (cg + 1 <= gr1) ? __expf(s[nb][3]) : 0.f;
            } else {
                p0 = __expf(s[nb][0]); p1 = __expf(s[nb][1]);
                p2 = __expf(s[nb][2]); p3 = __expf(s[nb][3]);
            }
            l0 += p0 + p1;
            l1 += p2 + p3;
            s[nb][0] = p0; s[nb][1] = p1; s[nb][2] = p2; s[nb][3] = p3;
        }

        if (more) CPA_WAIT1(); else CPA_WAIT0();   // gv(t) done: VP(t) landed
        __syncthreads();

        // ---- MMA2: O += P @ V over this key-half; P via shfl transpose ----
#pragma unroll
        for (int kc = 0; kc < 4; kc++) {
            u32 u0 = f2tf(s[kc][0]), u1 = f2tf(s[kc][1]);
            u32 u2 = f2tf(s[kc][2]), u3 = f2tf(s[kc][3]);
            u32 x0 = __shfl_sync(0xffffffffu, u0, srcA);
            u32 x1 = __shfl_sync(0xffffffffu, u1, srcA);
            u32 x2 = __shfl_sync(0xffffffffu, u2, srcA);
            u32 x3 = __shfl_sync(0xffffffffu, u3, srcA);
            u32 y0 = __shfl_sync(0xffffffffu, u0, srcB);
            u32 y1 = __shfl_sync(0xffffffffu, u1, srcB);
            u32 y2 = __shfl_sync(0xffffffffu, u2, srcB);
            u32 y3 = __shfl_sync(0xffffffffu, u3, srcB);
            u32 a[4];
            a[0] = comp ? x1 : x0;
            a[1] = comp ? x3 : x2;
            a[2] = comp ? y1 : y0;
            a[3] = comp ? y3 : y2;
            const int kcg = cw * 4 + kc;
#pragma unroll
            for (int nb = 0; nb < 8; nb++) {
                const int d = nb * 8 + gid;
                uint2 vb = *(const uint2*)&sm[VP_O + kcg*512 + d*8 + (sw << 1)];
                mma8(o[nb], a, vb.x, vb.y);
            }
        }
        __syncthreads();   // all MMA2 done: VP(t) free

        // ---- refill VP with t+1 (hidden under next MMA1) ----
        if (more) {
            const u32* vsrc = g_VP + (b * TILES + t + 1) * 4096;
#pragma unroll
            for (int j = 0; j < 4; j++) {
                const int g = tid * 4 + j;
                cpa16(sb + (VP_O + g * 4) * 4, vsrc + g * 4);
            }
            CPA_COMMIT();
        }
        // outstanding = [gk(t+1), gv(t+1)] (or none on last tile)
    }

    // ---- epilogue: atomic-combine partials ----
    l0 += __shfl_xor_sync(0xffffffffu, l0, 1);
    l0 += __shfl_xor_sync(0xffffffffu, l0, 2);
    l1 += __shfl_xor_sync(0xffffffffu, l1, 1);
    l1 += __shfl_xor_sync(0xffffffffu, l1, 2);
    if (tig == 0) {
        atomicAdd(&g_Lsum[b * S_ + gr0], l0);
        atomicAdd(&g_Lsum[b * S_ + gr1], l1);
    }
    float* og0 = O + ((size_t)(b * S_ + gr0)) * D_;
    float* og1 = O + ((size_t)(b * S_ + gr1)) * D_;
#pragma unroll
    for (int nb = 0; nb < 8; nb++) {
        const int col = nb * 8 + 2 * tig;
        atomicAdd(og0 + col,     o[nb][0]);
        atomicAdd(og0 + col + 1, o[nb][1]);
        atomicAdd(og1 + col,     o[nb][2]);
        atomicAdd(og1 + col + 1, o[nb][3]);
    }
}

extern "C" void kernel_launch(void* const* d_in, const int* in_sizes, int n_in,
                              void* d_out, int out_size) {
    const float* q = (const float*)d_in[0];
    const float* k = (const float*)d_in[1];
    const float* v = (const float*)d_in[2];
    float* o = (float*)d_out;
    const int n4 = (B_ * S_ * D_) / 4;
    cudaFuncSetAttribute(fa_chunk, cudaFuncAttributeMaxDynamicSharedMemorySize, SM_BYTES);
    prep_k<<<dim3(TILES, B_), NT>>>(q, k, v, o);
    fa_chunk<<<dim3(NCHUNK, B_), NT, SM_BYTES>>>(o);
    norm_k<<<(n4 + 255) / 256, 256>>>(o, n4);
}

// round 17
// speedup vs baseline: 1.0322x; 1.0322x over previous
#include <cuda_runtime.h>
#include <math.h>
#include <stdint.h>

#define B_  8
#define S_  2048
#define D_  64
#define BM  64
#define BN  64
#define NT  256
#define CW  8           // kv tiles per chunk
#define NCHUNK 80       // chunks per batch
#define TILES 32        // 64-row tiles per batch
#define BSD (B_ * S_ * D_)

typedef uint32_t u32;

// smem word offsets
#define QP_O 0                    // [8kc][64r][4tig] uint4 (hi,hi+4,lo,lo+4)
#define KP_O (QP_O + 8192)
#define VP_O (KP_O + 8192)        // [8kcv][64d][8] packed uint2 (V[k],V[k+4])
#define SM_WORDS (VP_O + 4096)
#define SM_BYTES (SM_WORDS * 4)   // 81920 B -> 2 CTAs/SM

__device__ float g_Lsum[B_ * S_];
__device__ float g_Opart[4 * BSD];        // partial O per chunk-slot (16 MB)
__device__ u32 g_QP[B_ * TILES * 8192];
__device__ u32 g_KP[B_ * TILES * 8192];
__device__ u32 g_VP[B_ * TILES * 4096];

__device__ __forceinline__ u32 f2tf(float x) {
    u32 r; asm("cvt.rna.tf32.f32 %0, %1;" : "=r"(r) : "f"(x)); return r;
}
__device__ __forceinline__ u32 smem_u32(const void* p) {
    u32 a; asm("{ .reg .u64 t; cvta.to.shared.u64 t, %1; cvt.u32.u64 %0, t; }" : "=r"(a) : "l"(p));
    return a;
}
__device__ __forceinline__ void cpa16(u32 dst, const void* src) {
    asm volatile("cp.async.cg.shared.global [%0], [%1], 16;" :: "r"(dst), "l"(src) : "memory");
}
#define CPA_COMMIT() asm volatile("cp.async.commit_group;" ::: "memory")
#define CPA_WAIT1()  asm volatile("cp.async.wait_group 1;" ::: "memory")
#define CPA_WAIT0()  asm volatile("cp.async.wait_group 0;" ::: "memory")

__device__ __forceinline__ void mma8(float* d, const u32* a, u32 b0, u32 b1) {
    asm volatile("mma.sync.aligned.m16n8k8.row.col.f32.tf32.tf32.f32 "
        "{%0,%1,%2,%3}, {%4,%5,%6,%7}, {%8,%9}, {%0,%1,%2,%3};"
        : "+f"(d[0]), "+f"(d[1]), "+f"(d[2]), "+f"(d[3])
        : "r"(a[0]), "r"(a[1]), "r"(a[2]), "r"(a[3]), "r"(b0), "r"(b1));
}

// Prep: pack one tensor-tile per block. Grid (TILES, B_, 3): z=0 Q, z=1 K, z=2 V+Lsum0.
__global__ void prep_k(const float* __restrict__ Q, const float* __restrict__ K,
                       const float* __restrict__ V)
{
    const int blk = blockIdx.x, b = blockIdx.y, z = blockIdx.z;
    const int tid = threadIdx.x;
    const int row = tid & 63, db = (tid >> 6) * 16;
    const int rot = (row >> 1) & 3;

    if (z < 2) {
        const float* srcp = (z == 0 ? Q : K) + ((size_t)(b * S_ + blk * 64 + row)) * D_ + db;
        u32* dst = (z == 0 ? g_QP : g_KP) + (b * TILES + blk) * 8192;
        const float4* src = (const float4*)srcp;
        float e[16];
#pragma unroll
        for (int j = 0; j < 4; j++) { float4 x = src[j]; e[4*j]=x.x; e[4*j+1]=x.y; e[4*j+2]=x.z; e[4*j+3]=x.w; }
#pragma unroll
        for (int cc = 0; cc < 2; cc++) {
            const int kc = (db >> 3) + cc;
#pragma unroll
            for (int j = 0; j < 4; j++) {
                float h0f = e[cc*8 + j], h1f = e[cc*8 + j + 4];
                u32 h0 = f2tf(h0f), h1 = f2tf(h1f);
                u32 l0w = f2tf(h0f - __uint_as_float(h0));
                u32 l1w = f2tf(h1f - __uint_as_float(h1));
                *(uint4*)&dst[kc*1024 + row*16 + (((j + rot) & 3) << 2)] =
                    make_uint4(h0, h1, l0w, l1w);
            }
        }
    } else {
        const float4* src = (const float4*)(V + ((size_t)(b * S_ + blk * 64 + row)) * D_ + db);
        float e[16];
#pragma unroll
        for (int j = 0; j < 4; j++) { float4 x = src[j]; e[4*j]=x.x; e[4*j+1]=x.y; e[4*j+2]=x.z; e[4*j+3]=x.w; }
        u32* vdst = g_VP + (b * TILES + blk) * 4096;
        const int kcv = row >> 3, tv = row & 3, sl = (row >> 2) & 1;
#pragma unroll
        for (int i = 0; i < 16; i++) {
            const int d = db + i;
            vdst[kcv*512 + d*8 + (((tv + (d >> 1)) & 3) << 1) + sl] = f2tf(e[i]);
        }
        const int gidx = (b * TILES + blk) * NT + tid;
        if (gidx < (B_ * S_) / 4)
            ((float4*)g_Lsum)[gidx] = make_float4(0.f, 0.f, 0.f, 0.f);
    }
}

// Sum valid chunk-slot partials (slot c valid iff c <= qb>>3), normalize.
__global__ void norm_k(float* __restrict__ out, int n4) {
    int i = blockIdx.x * blockDim.x + threadIdx.x;
    if (i >= n4) return;
    const int r   = i >> 4;                 // global row (b*S + row)
    const int ns  = ((r & (S_ - 1)) >> 9) + 1;   // (qb>>3)+1
    const float4* P4 = (const float4*)g_Opart;
    float4 a = P4[i];
    for (int s2 = 1; s2 < ns; s2++) {
        float4 v = P4[s2 * (BSD / 4) + i];
        a.x += v.x; a.y += v.y; a.z += v.z; a.w += v.w;
    }
    const float inv = 1.f / g_Lsum[r];
    a.x *= inv; a.y *= inv; a.z *= inv; a.w *= inv;
    ((float4*)out)[i] = a;
}

// Causal flash attention, mma.sync tf32 (3xtf32 QK^T, 1xtf32 PV), split-K chunks.
// Partial O goes to g_Opart[chunk] via coalesced STG (no atomics).
__global__ __launch_bounds__(NT, 2) void fa_chunk()
{
    extern __shared__ u32 sm[];
    const u32 sb = smem_u32(sm);
    const int tid  = threadIdx.x;
    const int lane = tid & 31;
    const int gid  = lane >> 2;
    const int tig  = lane & 3;
    const int rw   = (tid >> 5) >> 1;
    const int cw   = (tid >> 5) & 1;
    const int b    = blockIdx.y;

    // ---- decode (qb, chunk); longest chunks first ----
    int qb, c;
    {
        const int i = NCHUNK - 1 - blockIdx.x;
        if (i < 8)       { qb = i; c = 0; }
        else if (i < 24) { int j = i - 8;  qb = 8  + (j >> 1); c = j & 1; }
        else if (i < 48) { int j = i - 24; qb = 16 + j / 3;    c = j - 3 * (j / 3); }
        else             { int j = i - 48; qb = 24 + (j >> 2); c = j & 3; }
    }
    const int t0 = c * CW;
    const int t1 = min(t0 + CW, qb + 1);
    const int qbase = qb * BM;
    const int rq   = rw * 16 + gid;
    const int sw   = (tig + (gid >> 1)) & 3;
    const int srcA = (lane & ~3) | (tig >> 1);
    const int srcB = srcA + 2;
    const u32 comp = tig & 1;

    // ---- prologue: cp.async QP + KP(t0) as one group, VP(t0) as another ----
    {
        const u32* qsrc = g_QP + (b * TILES + qb) * 8192;
        const u32* ksrc = g_KP + (b * TILES + t0) * 8192;
#pragma unroll
        for (int j = 0; j < 8; j++) {
            const int g = tid * 8 + j;
            cpa16(sb + (QP_O + g * 4) * 4, qsrc + g * 4);
        }
#pragma unroll
        for (int j = 0; j < 8; j++) {
            const int g = tid * 8 + j;
            cpa16(sb + (KP_O + g * 4) * 4, ksrc + g * 4);
        }
        CPA_COMMIT();
        const u32* vsrc = g_VP + (b * TILES + t0) * 4096;
#pragma unroll
        for (int j = 0; j < 4; j++) {
            const int g = tid * 4 + j;
            cpa16(sb + (VP_O + g * 4) * 4, vsrc + g * 4);
        }
        CPA_COMMIT();
    }

    float o[8][4];
#pragma unroll
    for (int nb = 0; nb < 8; nb++)
#pragma unroll
        for (int cc = 0; cc < 4; cc++) o[nb][cc] = 0.f;
    float l0 = 0.f, l1 = 0.f;
    const int gr0 = qbase + rq, gr1 = gr0 + 8;

    for (int t = t0; t < t1; t++) {
        const bool more = (t + 1 < t1);
        CPA_WAIT1();       // QP + KP(t) landed
        __syncthreads();

        // ---- MMA1: S = Q @ K^T (3xtf32), this warp's 32-key half ----
        float s[4][4];
#pragma unroll
        for (int nb = 0; nb < 4; nb++)
#pragma unroll
            for (int cc = 0; cc < 4; cc++) s[nb][cc] = 0.f;
#pragma unroll
        for (int kc = 0; kc < 8; kc++) {
            uint4 qa = *(const uint4*)&sm[QP_O + kc*1024 + rq*16 + (sw << 2)];
            uint4 qc = *(const uint4*)&sm[QP_O + kc*1024 + (rq+8)*16 + (sw << 2)];
            u32 ah[4] = { qa.x, qc.x, qa.y, qc.y };
            u32 al[4] = { qa.z, qc.z, qa.w, qc.w };
#pragma unroll
            for (int nb = 0; nb < 4; nb++) {
                const int key = cw * 32 + nb * 8 + gid;
                uint4 kb = *(const uint4*)&sm[KP_O + kc*1024 + key*16 + (sw << 2)];
                mma8(s[nb], ah, kb.x, kb.y);
                mma8(s[nb], al, kb.x, kb.y);
                mma8(s[nb], ah, kb.z, kb.w);
            }
        }
        __syncthreads();   // KP(t) free

        if (more) {
            const u32* ksrc = g_KP + (b * TILES + t + 1) * 8192;
#pragma unroll
            for (int j = 0; j < 8; j++) {
                const int g = tid * 8 + j;
                cpa16(sb + (KP_O + g * 4) * 4, ksrc + g * 4);
            }
            CPA_COMMIT();
        }

        // ---- exp (+ causal mask on diagonal tile), l accumulation ----
        const bool diag = (t == qb);
#pragma unroll
        for (int nb = 0; nb < 4; nb++) {
            const int cg = t * BN + cw * 32 + nb * 8 + 2 * tig;
            float p0, p1, p2, p3;
            if (diag) {
                p0 = (cg     <= gr0) ? __expf(s[nb][0]) : 0.f;
                p1 = (cg + 1 <= gr0) ? __expf(s[nb][1]) : 0.f;
                p2 = (cg     <= gr1) ? __expf(s[nb][2]) : 0.f;
                p3 = (cg + 1 <= gr1) ? __expf(s[nb][3]) : 0.f;
            } else {
                p0 = __expf(s[nb][0]); p1 = __expf(s[nb][1]);
                p2 = __expf(s[nb][2]); p3 = __expf(s[nb][3]);
            }
            l0 += p0 + p1;
            l1 += p2 + p3;
            s[nb][0] = p0; s[nb][1] = p1; s[nb][2] = p2; s[nb][3] = p3;
        }

        if (more) CPA_WAIT1(); else CPA_WAIT0();   // VP(t) landed
        __syncthreads();

        // ---- MMA2: O += P @ V over this key-half; P via shfl transpose ----
#pragma unroll
        for (int kc = 0; kc < 4; kc++) {
            u32 u0 = f2tf(s[kc][0]), u1 = f2tf(s[kc][1]);
            u32 u2 = f2tf(s[kc][2]), u3 = f2tf(s[kc][3]);
            u32 x0 = __shfl_sync(0xffffffffu, u0, srcA);
            u32 x1 = __shfl_sync(0xffffffffu, u1, srcA);
            u32 x2 = __shfl_sync(0xffffffffu, u2, srcA);
            u32 x3 = __shfl_sync(0xffffffffu, u3, srcA);
            u32 y0 = __shfl_sync(0xffffffffu, u0, srcB);
            u32 y1 = __shfl_sync(0xffffffffu, u1, srcB);
            u32 y2 = __shfl_sync(0xffffffffu, u2, srcB);
            u32 y3 = __shfl_sync(0xffffffffu, u3, srcB);
            u32 a[4];
            a[0] = comp ? x1 : x0;
            a[1] = comp ? x3 : x2;
            a[2] = comp ? y1 : y0;
            a[3] = comp ? y3 : y2;
            const int kcg = cw * 4 + kc;
#pragma unroll
            for (int nb = 0; nb < 8; nb++) {
                const int d = nb * 8 + gid;
                uint2 vb = *(const uint2*)&sm[VP_O + kcg*512 + d*8 + (sw << 1)];
                mma8(o[nb], a, vb.x, vb.y);
            }
        }
        __syncthreads();   // VP(t) free

        if (more) {
            const u32* vsrc = g_VP + (b * TILES + t + 1) * 4096;
#pragma unroll
            for (int j = 0; j < 4; j++) {
                const int g = tid * 4 + j;
                cpa16(sb + (VP_O + g * 4) * 4, vsrc + g * 4);
            }
            CPA_COMMIT();
        }
    }

    // ---- epilogue: l atomics (tiny); O via smem combine + coalesced STG ----
    l0 += __shfl_xor_sync(0xffffffffu, l0, 1);
    l0 += __shfl_xor_sync(0xffffffffu, l0, 2);
    l1 += __shfl_xor_sync(0xffffffffu, l1, 1);
    l1 += __shfl_xor_sync(0xffffffffu, l1, 2);
    if (tig == 0) {
        atomicAdd(&g_Lsum[b * S_ + gr0], l0);
        atomicAdd(&g_Lsum[b * S_ + gr1], l1);
    }
    float* smf = (float*)sm;     // alias QP region: 64x64 O exchange (16 KB)
    if (cw == 1) {
#pragma unroll
        for (int nb = 0; nb < 8; nb++) {
            const int col = nb * 8 + 2 * tig;
            *(float2*)&smf[rq*64 + col]     = make_float2(o[nb][0], o[nb][1]);
            *(float2*)&smf[(rq+8)*64 + col] = make_float2(o[nb][2], o[nb][3]);
        }
    }
    __syncthreads();
    if (cw == 0) {
#pragma unroll
        for (int nb = 0; nb < 8; nb++) {
            const int col = nb * 8 + 2 * tig;
            float2 w0 = *(const float2*)&smf[rq*64 + col];
            float2 w1 = *(const float2*)&smf[(rq+8)*64 + col];
            *(float2*)&smf[rq*64 + col]     = make_float2(o[nb][0] + w0.x, o[nb][1] + w0.y);
            *(float2*)&smf[(rq+8)*64 + col] = make_float2(o[nb][2] + w1.x, o[nb][3] + w1.y);
        }
    }
    __syncthreads();
    // coalesced dump: 1024 float4, rows qbase..qbase+63 contiguous in g_Opart[c]
    {
        float4* dst = (float4*)(g_Opart + (size_t)c * BSD + ((size_t)(b * S_ + qbase)) * D_);
        const float4* srcv = (const float4*)smf;
#pragma unroll
        for (int j = 0; j < 4; j++)
            dst[j * NT + tid] = srcv[j * NT + tid];
    }
}

extern "C" void kernel_launch(void* const* d_in, const int* in_sizes, int n_in,
                              void* d_out, int out_size) {
    const float* q = (const float*)d_in[0];
    const float* k = (const float*)d_in[1];
    const float* v = (const float*)d_in[2];
    float* o = (float*)d_out;
    const int n4 = BSD / 4;
    cudaFuncSetAttribute(fa_chunk, cudaFuncAttributeMaxDynamicSharedMemorySize, SM_BYTES);
    prep_k<<<dim3(TILES, B_, 3), NT>>>(q, k, v);
    fa_chunk<<<dim3(NCHUNK, B_), NT, SM_BYTES>>>();
    norm_k<<<(n4 + 255) / 256, 256>>>(o, n4);
}